// round 1
// baseline (speedup 1.0000x reference)
#include <cuda_runtime.h>
#include <cuda_bf16.h>

// Fused 2-layer LSTM + MLP head, persistent kernel.
// Grid: 128 CTAs x 512 threads. Each CTA owns NB=4 batch rows and runs all
// T=1000 timesteps locally. All LSTM weights live in per-thread registers
// (split-k across threads); h/c state and the concatenated step-input vector
// live in SMEM transposed so one LDS.128 broadcasts all 4 batch values.

#define T_STEPS 1000
#define NB 4

__device__ __forceinline__ float sigf(float x) {
    // 1/(1+2^(-x*log2e)) : FMUL + MUFU.EX2 + FADD + MUFU.RCP + FMUL
    float e = exp2f(-1.4426950408889634f * x);
    return __fdividef(1.0f, 1.0f + e);
}
__device__ __forceinline__ float tanh_fast(float x) {
    // clamp so exp2 cannot overflow to inf (NaN in the ratio)
    x = fminf(16.0f, fmaxf(-16.0f, x));
    float e = exp2f(-2.8853900817779268f * x);   // exp(-2x)
    return __fdividef(1.0f - e, 1.0f + e);
}

__global__ void __launch_bounds__(512, 1)
audio_lstm_kernel(const float* __restrict__ x,
                  const float* __restrict__ w_ih1, const float* __restrict__ w_hh1,
                  const float* __restrict__ b_ih1, const float* __restrict__ b_hh1,
                  const float* __restrict__ w_ih2, const float* __restrict__ w_hh2,
                  const float* __restrict__ b_ih2, const float* __restrict__ b_hh2,
                  const float* __restrict__ w_fc1, const float* __restrict__ b_fc1,
                  const float* __restrict__ w_fc2, const float* __restrict__ b_fc2,
                  float* __restrict__ out)
{
    // v1T[k][b]: concat(x_t[26], h1[64]) transposed, 16B rows for float4 reads
    __shared__ __align__(16) float v1T[90][NB];
    // v2T[k][b]: concat(h1_t[64], h2[32])
    __shared__ __align__(16) float v2T[96][NB];
    __shared__ float sg1[NB][256];   // activated L1 gates (i,f,g,o blocks of 64)
    __shared__ float sg2[NB][128];   // activated L2 gates (blocks of 32)
    __shared__ float c1s[NB][64];
    __shared__ float c2s[NB][32];
    __shared__ float sf[NB][16];

    const int tid = threadIdx.x;
    const int bbase = blockIdx.x * NB;

    // ---- Layer-1 mapping: gate g1 = tid>>1, k split even/odd across lane pair
    const int g1   = tid >> 1;
    const int half = tid & 1;
    // ---- Layer-2 mapping: gate g2 = tid>>2, k split mod-4 across lane quad
    const int g2 = tid >> 2;
    const int q  = tid & 3;

    // Load weights into registers (one-time; uncoalesced is fine)
    float w1[45];
#pragma unroll
    for (int i = 0; i < 45; i++) {
        int k = 2 * i + half;
        w1[i] = (k < 26) ? w_ih1[g1 * 26 + k] : w_hh1[g1 * 64 + (k - 26)];
    }
    const float bias1 = b_ih1[g1] + b_hh1[g1];

    float w2[24];
#pragma unroll
    for (int i = 0; i < 24; i++) {
        int k = 4 * i + q;
        w2[i] = (k < 64) ? w_ih2[g2 * 64 + k] : w_hh2[g2 * 32 + (k - 64)];
    }
    const float bias2 = b_ih2[g2] + b_hh2[g2];

    // Zero state
    for (int idx = tid; idx < 90 * NB; idx += 512) ((float*)v1T)[idx] = 0.0f;
    for (int idx = tid; idx < 96 * NB; idx += 512) ((float*)v2T)[idx] = 0.0f;
    if (tid < NB * 64) ((float*)c1s)[tid] = 0.0f;
    if (tid < NB * 32) ((float*)c2s)[tid] = 0.0f;

    // x layout: x[b][i][t]  (b stride 26*T, i stride T)
    const int xi = tid % 26;
    const int xb = tid / 26;     // valid for tid < 104
    const float* xptr = x + (size_t)(bbase + xb) * 26 * T_STEPS + (size_t)xi * T_STEPS;
    if (tid < 104) v1T[xi][xb] = xptr[0];
    __syncthreads();

    const int l1type = g1 >> 6;   // 0:i 1:f 2:g 3:o  (uniform per warp)
    const int l2type = g2 >> 5;   // uniform per warp

    float xr = 0.0f;
    for (int t = 0; t < T_STEPS; t++) {
        // Prefetch next x while we compute (L1-resident after first touch)
        if (tid < 104 && t + 1 < T_STEPS) xr = xptr[t + 1];

        // ================= Phase A: layer-1 gates =================
        float a0 = 0.f, a1 = 0.f, a2 = 0.f, a3 = 0.f;
#pragma unroll
        for (int i = 0; i < 45; i++) {
            float4 v = *(const float4*)v1T[2 * i + half];
            float w = w1[i];
            a0 = fmaf(w, v.x, a0);
            a1 = fmaf(w, v.y, a1);
            a2 = fmaf(w, v.z, a2);
            a3 = fmaf(w, v.w, a3);
        }
        a0 += __shfl_xor_sync(0xffffffffu, a0, 1);
        a1 += __shfl_xor_sync(0xffffffffu, a1, 1);
        a2 += __shfl_xor_sync(0xffffffffu, a2, 1);
        a3 += __shfl_xor_sync(0xffffffffu, a3, 1);
        // half==0 activates b=0,1 ; half==1 activates b=2,3 (splits MUFU work)
        {
            float p0 = (half ? a2 : a0) + bias1;
            float p1 = (half ? a3 : a1) + bias1;
            float r0, r1;
            if (l1type == 2) { r0 = tanh_fast(p0); r1 = tanh_fast(p1); }
            else             { r0 = sigf(p0);      r1 = sigf(p1);      }
            int b0 = half * 2;
            sg1[b0][g1]     = r0;
            sg1[b0 + 1][g1] = r1;
        }
        __syncthreads();   // #1

        // ============ Phase B: layer-1 state update + x stage ============
        if (tid < 256) {
            int b = tid >> 6, i = tid & 63;
            float ig = sg1[b][i];
            float fg = sg1[b][64 + i];
            float gg = sg1[b][128 + i];
            float og = sg1[b][192 + i];
            float c = fmaf(fg, c1s[b][i], ig * gg);
            c1s[b][i] = c;
            float h = og * tanh_fast(c);
            v1T[26 + i][b] = h;   // for layer-1 next step
            v2T[i][b]      = h;   // for layer-2 this step
        }
        if (tid < 104 && t + 1 < T_STEPS) v1T[xi][xb] = xr;
        __syncthreads();   // #2

        // ================= Phase C: layer-2 gates =================
        float s0 = 0.f, s1 = 0.f, s2 = 0.f, s3 = 0.f;
#pragma unroll
        for (int i = 0; i < 24; i++) {
            float4 v = *(const float4*)v2T[4 * i + q];
            float w = w2[i];
            s0 = fmaf(w, v.x, s0);
            s1 = fmaf(w, v.y, s1);
            s2 = fmaf(w, v.z, s2);
            s3 = fmaf(w, v.w, s3);
        }
        s0 += __shfl_xor_sync(0xffffffffu, s0, 1); s0 += __shfl_xor_sync(0xffffffffu, s0, 2);
        s1 += __shfl_xor_sync(0xffffffffu, s1, 1); s1 += __shfl_xor_sync(0xffffffffu, s1, 2);
        s2 += __shfl_xor_sync(0xffffffffu, s2, 1); s2 += __shfl_xor_sync(0xffffffffu, s2, 2);
        s3 += __shfl_xor_sync(0xffffffffu, s3, 1); s3 += __shfl_xor_sync(0xffffffffu, s3, 2);
        {
            float p = (q == 0) ? s0 : (q == 1) ? s1 : (q == 2) ? s2 : s3;
            p += bias2;
            float r = (l2type == 2) ? tanh_fast(p) : sigf(p);
            sg2[q][g2] = r;   // lane q handles batch b=q
        }
        __syncthreads();   // #3

        // ============ Phase D: layer-2 state update ============
        if (tid < 128) {
            int b = tid >> 5, j = tid & 31;
            float ig = sg2[b][j];
            float fg = sg2[b][32 + j];
            float gg = sg2[b][64 + j];
            float og = sg2[b][96 + j];
            float c = fmaf(fg, c2s[b][j], ig * gg);
            c2s[b][j] = c;
            v2T[64 + j][b] = og * tanh_fast(c);
        }
        // no barrier needed here: next-iter readers of v2T[64+]/sg2 are
        // separated from these writes by barriers #1/#2 of the next iteration
    }
    __syncthreads();

    // ================= MLP head =================
    if (tid < 64) {
        int b = tid >> 4, j = tid & 15;
        float s = b_fc1[j];
#pragma unroll
        for (int k = 0; k < 32; k++) s = fmaf(v2T[64 + k][b], w_fc1[j * 32 + k], s);
        sf[b][j] = fmaxf(s, 0.0f);
    }
    __syncthreads();
    if (tid < 40) {
        int b = tid / 10, o = tid % 10;
        float s = b_fc2[o];
#pragma unroll
        for (int j = 0; j < 16; j++) s = fmaf(sf[b][j], w_fc2[o * 16 + j], s);
        out[(bbase + b) * 10 + o] = s;
    }
}

extern "C" void kernel_launch(void* const* d_in, const int* in_sizes, int n_in,
                              void* d_out, int out_size)
{
    const float* x     = (const float*)d_in[0];
    const float* w_ih1 = (const float*)d_in[1];
    const float* w_hh1 = (const float*)d_in[2];
    const float* b_ih1 = (const float*)d_in[3];
    const float* b_hh1 = (const float*)d_in[4];
    const float* w_ih2 = (const float*)d_in[5];
    const float* w_hh2 = (const float*)d_in[6];
    const float* b_ih2 = (const float*)d_in[7];
    const float* b_hh2 = (const float*)d_in[8];
    const float* w_fc1 = (const float*)d_in[9];
    const float* b_fc1 = (const float*)d_in[10];
    const float* w_fc2 = (const float*)d_in[11];
    const float* b_fc2 = (const float*)d_in[12];
    float* out = (float*)d_out;

    audio_lstm_kernel<<<128, 512>>>(x, w_ih1, w_hh1, b_ih1, b_hh1,
                                    w_ih2, w_hh2, b_ih2, b_hh2,
                                    w_fc1, b_fc1, w_fc2, b_fc2, out);
}

// round 2
// speedup vs baseline: 1.7634x; 1.7634x over previous
#include <cuda_runtime.h>

// Fused 2-layer LSTM + MLP, persistent warp-specialized pipelined kernel.
// Grid 128 x 384 threads. CTA owns 4 batch rows, runs all 1000 steps.
// Threads 0-255  = L1 group: thread = (gate-pair gp, k-half kh). 2 gates x 45 k
//                  weights in regs, batch-packed fma.rn.f32x2.
// Threads 256-383 = L2 group: thread = (gate-pair, k-parity). 2 gates x 48 k.
// L2 runs one timestep behind L1 (skewed pipeline, double-buffered h1).

#define T_STEPS 1000

__device__ __forceinline__ float sigf(float x) {
    float e = exp2f(-1.4426950408889634f * x);
    return __fdividef(1.0f, 1.0f + e);
}
__device__ __forceinline__ float tanh_fast(float x) {
    x = fminf(16.0f, fmaxf(-16.0f, x));
    float e = exp2f(-2.8853900817779268f * x);   // exp(-2x)
    return __fdividef(1.0f - e, 1.0f + e);
}
__device__ __forceinline__ double pk2(float lo, float hi) {
    double r; asm("mov.b64 %0, {%1,%2};" : "=d"(r) : "f"(lo), "f"(hi)); return r;
}
__device__ __forceinline__ void upk2(double v, float &lo, float &hi) {
    asm("mov.b64 {%0,%1}, %2;" : "=f"(lo), "=f"(hi) : "d"(v));
}
__device__ __forceinline__ void fma2(double &acc, double a, double b) {
    asm("fma.rn.f32x2 %0, %1, %2, %0;" : "+d"(acc) : "d"(a), "d"(b));
}

__global__ void __launch_bounds__(384, 1)
audio_lstm_kernel(const float* __restrict__ x,
                  const float* __restrict__ w_ih1, const float* __restrict__ w_hh1,
                  const float* __restrict__ b_ih1, const float* __restrict__ b_hh1,
                  const float* __restrict__ w_ih2, const float* __restrict__ w_hh2,
                  const float* __restrict__ b_ih2, const float* __restrict__ b_hh2,
                  const float* __restrict__ w_fc1, const float* __restrict__ b_fc1,
                  const float* __restrict__ w_fc2, const float* __restrict__ b_fc2,
                  float* __restrict__ out)
{
    // v1T[k][b]: x rows 0..25, h1 rows 26..89 (16B rows -> one LDS.128 = 4 batches)
    __shared__ __align__(16) float v1T[90][4];
    __shared__ __align__(16) float h1b[2][64][4];   // double-buffered h1 for L2
    __shared__ __align__(16) float h2T[32][4];      // h2 state
    __shared__ float sg1[4][256];
    __shared__ float sg2[4][128];
    __shared__ float sf[4][16];

    const int tid = threadIdx.x;
    const int bbase = blockIdx.x * 4;
    const bool isL1 = tid < 256;

    // Shared virtual registers between the two thread roles (keeps regcount ~96)
    float wA[48], wB[48];
    float biasA, biasB;
    float c = 0.0f;
    int gp, kh, gA;

    if (isL1) {
        gp = tid >> 1; kh = tid & 1;         // gates 2gp, 2gp+1 ; k-half kh
        gA = 2 * gp;
        const int gB = gA + 1;
#pragma unroll
        for (int i = 0; i < 48; i++) {
            int k = kh * 45 + i;
            float a = 0.f, b = 0.f;
            if (i < 45) {
                a = (k < 26) ? w_ih1[gA * 26 + k] : w_hh1[gA * 64 + (k - 26)];
                b = (k < 26) ? w_ih1[gB * 26 + k] : w_hh1[gB * 64 + (k - 26)];
            }
            wA[i] = a; wB[i] = b;
        }
        biasA = b_ih1[gA] + b_hh1[gA];
        biasB = b_ih1[gB] + b_hh1[gB];
    } else {
        const int u2 = tid - 256;
        gp = u2 >> 1; kh = u2 & 1;           // gates 2gp, 2gp+1 ; k parity kh
        gA = 2 * gp;
        const int gB = gA + 1;
#pragma unroll
        for (int i = 0; i < 48; i++) {
            int k = 2 * i + kh;
            wA[i] = (k < 64) ? w_ih2[gA * 64 + k] : w_hh2[gA * 32 + (k - 64)];
            wB[i] = (k < 64) ? w_ih2[gB * 64 + k] : w_hh2[gB * 32 + (k - 64)];
        }
        biasA = b_ih2[gA] + b_hh2[gA];
        biasB = b_ih2[gB] + b_hh2[gB];
    }

    // Zero recurrent state regions
    for (int idx = tid; idx < 90 * 4; idx += 384) ((float*)v1T)[idx] = 0.0f;
    for (int idx = tid; idx < 32 * 4; idx += 384) ((float*)h2T)[idx] = 0.0f;

    // x layout: x[b][i][t]
    const int xi = tid % 26;
    const int xb = tid / 26;
    const float* xptr = x + (size_t)(bbase + xb) * 26 * T_STEPS + (size_t)xi * T_STEPS;
    if (tid < 104) v1T[xi][xb] = xptr[0];
    __syncthreads();

    // Iterations 0..1000: L1 does step n (n<1000); L2 does step n-1 (n>=1).
    for (int n = 0; n <= T_STEPS; n++) {
        if (isL1) {
            if (n < T_STEPS) {
                const bool xact = (tid < 104) && (n + 1 < T_STEPS);
                float xr = 0.0f;
                if (xact) xr = xptr[n + 1];          // prefetch next x early

                double a01 = 0.0, a23 = 0.0, q01 = 0.0, q23 = 0.0;
                const float* vbase = &v1T[kh * 45][0];
#pragma unroll
                for (int i = 0; i < 45; i++) {
                    double2 v = *(const double2*)(vbase + 4 * i);
                    double wa = pk2(wA[i], wA[i]);
                    fma2(a01, wa, v.x); fma2(a23, wa, v.y);
                    double wb = pk2(wB[i], wB[i]);
                    fma2(q01, wb, v.x); fma2(q23, wb, v.y);
                }
                // combine with partner lane (other k-half): 4 shfls
                float pa0, pa1, pa2, pa3, pb0, pb1, pb2, pb3;
                upk2(a01, pa0, pa1); upk2(a23, pa2, pa3);
                upk2(q01, pb0, pb1); upk2(q23, pb2, pb3);
                float fA0 = (kh ? pa2 : pa0) + __shfl_xor_sync(0xffffffffu, kh ? pa0 : pa2, 1);
                float fA1 = (kh ? pa3 : pa1) + __shfl_xor_sync(0xffffffffu, kh ? pa1 : pa3, 1);
                float fB0 = (kh ? pb2 : pb0) + __shfl_xor_sync(0xffffffffu, kh ? pb0 : pb2, 1);
                float fB1 = (kh ? pb3 : pb1) + __shfl_xor_sync(0xffffffffu, kh ? pb1 : pb3, 1);
                fA0 += biasA; fA1 += biasA; fB0 += biasB; fB1 += biasB;
                float rA0, rA1, rB0, rB1;
                if ((gA >> 6) == 2) {                 // g-gate block: tanh
                    rA0 = tanh_fast(fA0); rA1 = tanh_fast(fA1);
                    rB0 = tanh_fast(fB0); rB1 = tanh_fast(fB1);
                } else {
                    rA0 = sigf(fA0); rA1 = sigf(fA1);
                    rB0 = sigf(fB0); rB1 = sigf(fB1);
                }
                const int bb = kh * 2;                // kh=0 -> batches 0,1 ; kh=1 -> 2,3
                sg1[bb][gA] = rA0; sg1[bb + 1][gA] = rA1;
                sg1[bb][gA + 1] = rB0; sg1[bb + 1][gA + 1] = rB1;
                asm volatile("bar.sync 1, 256;" ::: "memory");

                // state update: task (b = tid>>6, i = tid&63), c in register
                {
                    const int b = tid >> 6, i = tid & 63;
                    float ig = sg1[b][i];
                    float fg = sg1[b][64 + i];
                    float gg = sg1[b][128 + i];
                    float og = sg1[b][192 + i];
                    c = fmaf(fg, c, ig * gg);
                    float h = og * tanh_fast(c);
                    v1T[26 + i][b] = h;               // layer-1 next step
                    h1b[n & 1][i][b] = h;             // layer-2 (skewed) input
                }
                if (xact) v1T[xi][xb] = xr;
            }
        } else {
            if (n >= 1) {
                const float* h1base = &h1b[(n - 1) & 1][0][0];
                double a01 = 0.0, a23 = 0.0, q01 = 0.0, q23 = 0.0;
#pragma unroll
                for (int i = 0; i < 32; i++) {        // k = 2i+kh < 64 : h1
                    double2 v = *(const double2*)(h1base + 4 * (2 * i + kh));
                    double wa = pk2(wA[i], wA[i]);
                    fma2(a01, wa, v.x); fma2(a23, wa, v.y);
                    double wb = pk2(wB[i], wB[i]);
                    fma2(q01, wb, v.x); fma2(q23, wb, v.y);
                }
#pragma unroll
                for (int i = 32; i < 48; i++) {       // k = 2i+kh >= 64 : h2
                    double2 v = *(const double2*)&h2T[2 * i + kh - 64][0];
                    double wa = pk2(wA[i], wA[i]);
                    fma2(a01, wa, v.x); fma2(a23, wa, v.y);
                    double wb = pk2(wB[i], wB[i]);
                    fma2(q01, wb, v.x); fma2(q23, wb, v.y);
                }
                float pa0, pa1, pa2, pa3, pb0, pb1, pb2, pb3;
                upk2(a01, pa0, pa1); upk2(a23, pa2, pa3);
                upk2(q01, pb0, pb1); upk2(q23, pb2, pb3);
                float fA0 = (kh ? pa2 : pa0) + __shfl_xor_sync(0xffffffffu, kh ? pa0 : pa2, 1);
                float fA1 = (kh ? pa3 : pa1) + __shfl_xor_sync(0xffffffffu, kh ? pa1 : pa3, 1);
                float fB0 = (kh ? pb2 : pb0) + __shfl_xor_sync(0xffffffffu, kh ? pb0 : pb2, 1);
                float fB1 = (kh ? pb3 : pb1) + __shfl_xor_sync(0xffffffffu, kh ? pb1 : pb3, 1);
                fA0 += biasA; fA1 += biasA; fB0 += biasB; fB1 += biasB;
                float rA0, rA1, rB0, rB1;
                if ((gA >> 5) == 2) {
                    rA0 = tanh_fast(fA0); rA1 = tanh_fast(fA1);
                    rB0 = tanh_fast(fB0); rB1 = tanh_fast(fB1);
                } else {
                    rA0 = sigf(fA0); rA1 = sigf(fA1);
                    rB0 = sigf(fB0); rB1 = sigf(fB1);
                }
                const int bb = kh * 2;
                sg2[bb][gA] = rA0; sg2[bb + 1][gA] = rA1;
                sg2[bb][gA + 1] = rB0; sg2[bb + 1][gA + 1] = rB1;
                asm volatile("bar.sync 2, 128;" ::: "memory");

                {
                    const int u2 = tid - 256;
                    const int b = u2 >> 5, j = u2 & 31;
                    float ig = sg2[b][j];
                    float fg = sg2[b][32 + j];
                    float gg = sg2[b][64 + j];
                    float og = sg2[b][96 + j];
                    c = fmaf(fg, c, ig * gg);
                    float h = og * tanh_fast(c);
                    h2T[j][b] = h;
                }
            }
        }
        __syncthreads();
    }

    // ================= MLP head =================
    if (tid < 64) {
        const int b = tid >> 4, j = tid & 15;
        float s = b_fc1[j];
#pragma unroll
        for (int k2 = 0; k2 < 32; k2++) s = fmaf(h2T[k2][b], w_fc1[j * 32 + k2], s);
        sf[b][j] = fmaxf(s, 0.0f);
    }
    __syncthreads();
    if (tid < 40) {
        const int b = tid / 10, o = tid % 10;
        float s = b_fc2[o];
#pragma unroll
        for (int j = 0; j < 16; j++) s = fmaf(sf[b][j], w_fc2[o * 16 + j], s);
        out[(bbase + b) * 10 + o] = s;
    }
}

extern "C" void kernel_launch(void* const* d_in, const int* in_sizes, int n_in,
                              void* d_out, int out_size)
{
    const float* x     = (const float*)d_in[0];
    const float* w_ih1 = (const float*)d_in[1];
    const float* w_hh1 = (const float*)d_in[2];
    const float* b_ih1 = (const float*)d_in[3];
    const float* b_hh1 = (const float*)d_in[4];
    const float* w_ih2 = (const float*)d_in[5];
    const float* w_hh2 = (const float*)d_in[6];
    const float* b_ih2 = (const float*)d_in[7];
    const float* b_hh2 = (const float*)d_in[8];
    const float* w_fc1 = (const float*)d_in[9];
    const float* b_fc1 = (const float*)d_in[10];
    const float* w_fc2 = (const float*)d_in[11];
    const float* b_fc2 = (const float*)d_in[12];
    float* out = (float*)d_out;

    audio_lstm_kernel<<<128, 384>>>(x, w_ih1, w_hh1, b_ih1, b_hh1,
                                    w_ih2, w_hh2, b_ih2, b_hh2,
                                    w_fc1, b_fc1, w_fc2, b_fc2, out);
}